// round 1
// baseline (speedup 1.0000x reference)
#include <cuda_runtime.h>
#include <math.h>

#define Bn   32
#define Cn   256
#define Hn   64
#define Wn   64
#define HWn  4096
#define AUXn 64
#define RANKn 64
#define HIDn 256
#define OSn  8
#define PI_F 3.14159265358979323846f

// ---------------- scratch (static device globals; no allocs) ----------------
__device__ __align__(128) float d_gpart[Bn * 16 * Cn];   // per-(b,tile,c) spatial-sum partials
__device__ __align__(128) float d_av[Bn * HWn];          // channel mean
__device__ __align__(128) float d_mx[Bn * HWn];          // channel max
__device__ __align__(128) float d_h[Bn * HIDn];          // hidden activations
__device__ __align__(128) float d_mbc[Bn * Cn];          // m_base_c
__device__ __align__(128) float d_phic[Bn * RANKn];      // phi_c
__device__ __align__(128) float d_pco[Bn * 10];          // stencil coeffs: [p0..p3,center] x 2 planes
__device__ __align__(128) float d_Epart[8 * Cn * Bn];    // k-split partials of einsum
__device__ __align__(128) float d_sigc[Bn * Cn];         // sigmoid(c_m)
__device__ __align__(128) float d_convsig[Bn * HWn];     // sigmoid(conv)

// ---------------- K1: fused stats pass over x ----------------
// grid (16 tiles of 256 positions, Bn), 256 threads.
// Produces: d_gpart (spatial sum partials per c), d_av, d_mx (final).
__global__ void k1_stats(const float* __restrict__ x) {
    const int b    = blockIdx.y;
    const int tile = blockIdx.x;
    const int t    = threadIdx.x;
    const int warp = t >> 5, lane = t & 31;
    const int pos  = tile * 256 + t;

    __shared__ float wsum[8][Cn];   // 8 KB: per-warp, per-c partial sums

    const float* xb = x + (size_t)b * Cn * HWn + pos;
    float s = 0.f;
    float m = -3.402823466e38f;
    #pragma unroll 4
    for (int c = 0; c < Cn; c++) {
        float v = __ldg(xb + (size_t)c * HWn);
        s += v;
        m = fmaxf(m, v);
        float r = v;
        #pragma unroll
        for (int o = 16; o; o >>= 1) r += __shfl_xor_sync(0xffffffffu, r, o);
        if (lane == 0) wsum[warp][c] = r;
    }
    d_av[b * HWn + pos] = s * (1.f / (float)Cn);
    d_mx[b * HWn + pos] = m;
    __syncthreads();
    float g = 0.f;
    #pragma unroll
    for (int w = 0; w < 8; w++) g += wsum[w][t];
    d_gpart[(b * 16 + tile) * Cn + t] = g;
}

// ---------------- K2: per-batch MLP head ----------------
// grid (Bn), 256 threads. Computes h, m_base_c, phi_c/phi_s, s_m -> stencil coeffs.
__global__ void k2_mlp(const float* __restrict__ a,
                       const float* __restrict__ W_pre, const float* __restrict__ b_pre,
                       const float* __restrict__ W_bc,  const float* __restrict__ b_bc,
                       const float* __restrict__ W_bs,  const float* __restrict__ b_bs,
                       const float* __restrict__ W_pc,  const float* __restrict__ b_pc,
                       const float* __restrict__ W_ps,  const float* __restrict__ b_ps,
                       const float* __restrict__ W_Ws,  const float* __restrict__ b_Ws) {
    const int b = blockIdx.x;
    const int t = threadIdx.x;

    __shared__ float in_s[Cn + AUXn];   // 320
    __shared__ float h_s[HIDn];
    __shared__ float phic_s[RANKn], phis_s[RANKn];
    __shared__ float mbs_s[OSn], sm_s[OSn];
    __shared__ float sred[OSn * RANKn]; // 512

    // gather g = mean over HW
    {
        float g = 0.f;
        #pragma unroll
        for (int tl = 0; tl < 16; tl++) g += d_gpart[(b * 16 + tl) * Cn + t];
        in_s[t] = g * (1.f / (float)HWn);
        if (t < AUXn) in_s[Cn + t] = __ldg(a + b * AUXn + t);
    }
    __syncthreads();

    // h = relu(in @ W_pre + b_pre)
    {
        float acc = __ldg(b_pre + t);
        #pragma unroll 4
        for (int i = 0; i < Cn + AUXn; i++)
            acc = fmaf(in_s[i], __ldg(W_pre + i * HIDn + t), acc);
        float h = fmaxf(acc, 0.f);
        h_s[t] = h;
        d_h[b * HIDn + t] = h;
    }
    __syncthreads();

    // m_base_c (all threads)
    {
        float mb = __ldg(b_bc + t);
        #pragma unroll 4
        for (int k = 0; k < HIDn; k++)
            mb = fmaf(h_s[k], __ldg(W_bc + k * Cn + t), mb);
        d_mbc[b * Cn + t] = mb;
    }
    // phi_c / phi_s / m_base_s on low warps
    if (t < 32) {
        float p = __ldg(b_pc + t);
        #pragma unroll 4
        for (int k = 0; k < HIDn; k++)
            p = fmaf(h_s[k], __ldg(W_pc + k * RANKn + t), p);
        float w = 1.f + (PI_F - 1.f) * (float)t / 31.f;
        float u = p * w;
        phic_s[t]      = sinf(u);
        phic_s[t + 32] = cosf(u);
    } else if (t < 64) {
        int r = t - 32;
        float p = __ldg(b_ps + r);
        #pragma unroll 4
        for (int k = 0; k < HIDn; k++)
            p = fmaf(h_s[k], __ldg(W_ps + k * RANKn + r), p);
        float w = 1.f + (PI_F - 1.f) * (float)r / 31.f;
        float u = p * w;
        phis_s[r]      = sinf(u);
        phis_s[r + 32] = cosf(u);
    } else if (t < 64 + OSn) {
        int s = t - 64;
        float mbs = __ldg(b_bs + s);
        for (int k = 0; k < HIDn; k++)
            mbs = fmaf(h_s[k], __ldg(W_bs + k * OSn + s), mbs);
        mbs_s[s] = mbs;
    }
    __syncthreads();

    // Ws (8x64) * phi_s, elementwise into sred; also publish phi_c
    if (t < RANKn) d_phic[b * RANKn + t] = phic_s[t];
    #pragma unroll
    for (int o = t; o < OSn * RANKn; o += 256) {
        int r = o & 63;
        float ws = __ldg(b_Ws + o);
        #pragma unroll 4
        for (int k = 0; k < HIDn; k++)
            ws = fmaf(h_s[k], __ldg(W_Ws + k * (OSn * RANKn) + o), ws);
        sred[o] = ws * phis_s[r];
    }
    __syncthreads();

    if (t < OSn) {
        float sm = 0.f;
        #pragma unroll
        for (int r = 0; r < RANKn; r++) sm += sred[t * RANKn + r];
        sm_s[t] = mbs_s[t] * sm;
    }
    __syncthreads();

    if (t < OSn) {
        // p[j][d] = s_m[j*4+d] -> slots [j*5 + d]
        d_pco[b * 10 + (t >> 2) * 5 + (t & 3)] = sm_s[t];
    } else if (t < OSn + 2) {
        int j = t - OSn;
        float cc = -(sm_s[j * 4] + sm_s[j * 4 + 1] + sm_s[j * 4 + 2] + sm_s[j * 4 + 3]);
        d_pco[b * 10 + j * 5 + 4] = cc;
    }
}

// ---------------- K3: big einsum E[b,c] = sum_{k,r} h[b,k] phi[b,r] W_Wc[k, c*64+r] ----------------
// grid (32 c-tiles of 8, 8 k-splits of 32), 256 threads. lane = b, warp = c within tile.
// Each W_Wc element is read exactly once chip-wide (broadcast across the 32 b-lanes).
__global__ void k3_einsum(const float* __restrict__ W_Wc) {
    const int ct = blockIdx.x;   // c tile
    const int ks = blockIdx.y;   // k split
    const int t  = threadIdx.x;
    const int lane = t & 31;     // = b
    const int warp = t >> 5;
    const int c = ct * 8 + warp;

    __shared__ float h_s[32 * 33];    // [b][kk], padded
    __shared__ float phi_s[32 * 68];  // [b][r], padded (68*4 bytes = 16B multiple)

    for (int i = t; i < 32 * 32; i += 256) {
        int bb = i >> 5, kk = i & 31;
        h_s[bb * 33 + kk] = d_h[bb * HIDn + ks * 32 + kk];
    }
    for (int i = t; i < 32 * 64; i += 256) {
        int bb = i >> 6, r = i & 63;
        phi_s[bb * 68 + r] = d_phic[bb * RANKn + r];
    }
    __syncthreads();

    float acc = 0.f;
    const float* Wbase = W_Wc + (size_t)(ks * 32) * (Cn * RANKn) + c * RANKn;
    #pragma unroll 2
    for (int kk = 0; kk < 32; kk++) {
        float hk = h_s[lane * 33 + kk];
        const float4* w4 = (const float4*)(Wbase + (size_t)kk * (Cn * RANKn));
        float dot = 0.f;
        #pragma unroll
        for (int r4 = 0; r4 < 16; r4++) {
            float4 w = __ldg(&w4[r4]);                              // broadcast across lanes
            float4 p = *(const float4*)(phi_s + lane * 68 + r4 * 4);
            dot = fmaf(w.x, p.x, dot);
            dot = fmaf(w.y, p.y, dot);
            dot = fmaf(w.z, p.z, dot);
            dot = fmaf(w.w, p.w, dot);
        }
        acc = fmaf(hk, dot, acc);
    }
    d_Epart[(ks * Cn + c) * Bn + lane] = acc;   // [ks][c][b] -> coalesced over lane
}

// ---------------- K4: reduce partials + bias term -> sigmoid(c_m) ----------------
__global__ void k4_sigc(const float* __restrict__ b_Wc) {
    const int b = blockIdx.x;
    const int c = threadIdx.x;
    __shared__ float phi_s[RANKn];
    if (c < RANKn) phi_s[c] = d_phic[b * RANKn + c];
    __syncthreads();

    float e = 0.f;
    #pragma unroll
    for (int ks = 0; ks < 8; ks++) e += d_Epart[(ks * Cn + c) * Bn + b];

    float bias = 0.f;
    const float4* bw4 = (const float4*)(b_Wc + c * RANKn);
    #pragma unroll
    for (int r4 = 0; r4 < 16; r4++) {
        float4 w = __ldg(&bw4[r4]);
        float4 p = *(const float4*)(phi_s + r4 * 4);
        bias = fmaf(w.x, p.x, bias);
        bias = fmaf(w.y, p.y, bias);
        bias = fmaf(w.z, p.z, bias);
        bias = fmaf(w.w, p.w, bias);
    }
    float cm = d_mbc[b * Cn + c] * (e + bias);
    d_sigc[b * Cn + c] = 1.f / (1.f + expf(-cm));
}

// ---------------- K4b: 5-point stencil on (av, mx) -> sigmoid(conv) ----------------
__global__ void k4b_conv() {
    const int b  = blockIdx.y;
    const int hw = blockIdx.x * 256 + threadIdx.x;
    const int hh = hw >> 6, ww = hw & 63;
    __shared__ float pc[10];
    if (threadIdx.x < 10) pc[threadIdx.x] = d_pco[b * 10 + threadIdx.x];
    __syncthreads();

    const float* av = d_av + b * HWn;
    const float* mx = d_mx + b * HWn;

    float up_a = (hh > 0)      ? av[hw - Wn] : 0.f;
    float dn_a = (hh < Hn - 1) ? av[hw + Wn] : 0.f;
    float lf_a = (ww > 0)      ? av[hw - 1]  : 0.f;
    float rt_a = (ww < Wn - 1) ? av[hw + 1]  : 0.f;
    float ce_a = av[hw];
    float up_m = (hh > 0)      ? mx[hw - Wn] : 0.f;
    float dn_m = (hh < Hn - 1) ? mx[hw + Wn] : 0.f;
    float lf_m = (ww > 0)      ? mx[hw - 1]  : 0.f;
    float rt_m = (ww < Wn - 1) ? mx[hw + 1]  : 0.f;
    float ce_m = mx[hw];

    float conv = pc[0] * up_a + pc[1] * dn_a + pc[2] * lf_a + pc[3] * rt_a + pc[4] * ce_a
               + pc[5] * up_m + pc[6] * dn_m + pc[7] * lf_m + pc[8] * rt_m + pc[9] * ce_m;
    d_convsig[b * HWn + hw] = 1.f / (1.f + expf(-conv));
}

// ---------------- K5: output pass ----------------
// grid (4 hw4-tiles, Bn*8 c-groups), 256 threads. convsig held in registers across 32 channels.
__global__ void k5_out(const float* __restrict__ x, float* __restrict__ out) {
    const int t   = threadIdx.x;
    const int hw4 = blockIdx.x * 256 + t;      // 0..1023 (float4 units over HW)
    const int bcg = blockIdx.y;
    const int b   = bcg >> 3;
    const int cg  = bcg & 7;

    const float4 cv = ((const float4*)d_convsig)[b * (HWn / 4) + hw4];
    const float* sc = d_sigc + b * Cn + cg * 32;

    const size_t base = ((size_t)(b * Cn + cg * 32)) * (HWn / 4) + hw4;
    const float4* x4 = (const float4*)x;
    float4* o4 = (float4*)out;

    #pragma unroll 4
    for (int ci = 0; ci < 32; ci++) {
        float s = __ldg(sc + ci) + 1.f;
        float4 v = __ldg(&x4[base + (size_t)ci * (HWn / 4)]);
        float4 o;
        o.x = v.x * (s + cv.x);
        o.y = v.y * (s + cv.y);
        o.z = v.z * (s + cv.z);
        o.w = v.w * (s + cv.w);
        o4[base + (size_t)ci * (HWn / 4)] = o;
    }
}

// ---------------- launch ----------------
extern "C" void kernel_launch(void* const* d_in, const int* in_sizes, int n_in,
                              void* d_out, int out_size) {
    (void)in_sizes; (void)n_in; (void)out_size;
    const float* x     = (const float*)d_in[0];
    const float* a     = (const float*)d_in[1];
    const float* W_pre = (const float*)d_in[2];
    const float* b_pre = (const float*)d_in[3];
    const float* W_bc  = (const float*)d_in[4];
    const float* b_bc  = (const float*)d_in[5];
    const float* W_bs  = (const float*)d_in[6];
    const float* b_bs  = (const float*)d_in[7];
    const float* W_pc  = (const float*)d_in[8];
    const float* b_pc  = (const float*)d_in[9];
    const float* W_ps  = (const float*)d_in[10];
    const float* b_ps  = (const float*)d_in[11];
    const float* W_Wc  = (const float*)d_in[12];
    const float* b_Wc  = (const float*)d_in[13];
    const float* W_Ws  = (const float*)d_in[14];
    const float* b_Ws  = (const float*)d_in[15];
    float* out = (float*)d_out;

    k1_stats <<<dim3(16, Bn), 256>>>(x);
    k2_mlp   <<<Bn, 256>>>(a, W_pre, b_pre, W_bc, b_bc, W_bs, b_bs,
                           W_pc, b_pc, W_ps, b_ps, W_Ws, b_Ws);
    k3_einsum<<<dim3(32, 8), 256>>>(W_Wc);
    k4_sigc  <<<Bn, 256>>>(b_Wc);
    k4b_conv <<<dim3(16, Bn), 256>>>();
    k5_out   <<<dim3(4, Bn * 8), 256>>>(x, out);
}

// round 3
// speedup vs baseline: 1.2889x; 1.2889x over previous
#include <cuda_runtime.h>
#include <math.h>

#define Bn   32
#define Cn   256
#define Hn   64
#define Wn   64
#define HWn  4096
#define AUXn 64
#define RANKn 64
#define HIDn 256
#define OSn  8
#define PI_F 3.14159265358979323846f

// ---------------- scratch (static device globals; no allocs) ----------------
__device__ __align__(128) float d_gpart[Bn * 8 * Cn];    // per-(b,tile,c) spatial-sum partials
__device__ __align__(128) float d_av[Bn * HWn];          // channel mean
__device__ __align__(128) float d_mx[Bn * HWn];          // channel max
__device__ __align__(128) float d_h[Bn * HIDn];          // hidden activations
__device__ __align__(128) float d_mbc[Bn * Cn];          // m_base_c
__device__ __align__(128) float d_phic[Bn * RANKn];      // phi_c
__device__ __align__(128) float d_pco[Bn * 10];          // stencil coeffs
__device__ __align__(128) float d_Ep[Bn * 9 * Cn];       // [b][ks][c] einsum partials (ks=8 is bias)
__device__ __align__(128) float d_sigc[Bn * Cn];         // sigmoid(c_m)
__device__ __align__(128) float d_convsig[Bn * HWn];     // sigmoid(conv)

// ---------------- K1: fused stats pass over x ----------------
// grid (8 tiles of 512 positions, Bn), 256 threads (8 warps).
// Warp w owns channels [w*32, w*32+32); lanes cover 512 positions as 4x LDG.128.
// One shfl-reduce per (warp, c) -> 16x fewer shuffles per element than v1.
__global__ void k1_stats(const float* __restrict__ x) {
    const int b    = blockIdx.y;
    const int tile = blockIdx.x;
    const int t    = threadIdx.x;
    const int warp = t >> 5, lane = t & 31;
    const int pos0 = tile * 512;

    __shared__ float avp[8][512];
    __shared__ float mxp[8][512];

    const float4* xb = (const float4*)(x + (size_t)b * Cn * HWn);
    const int p4base = (pos0 >> 2) + lane;   // float4 index; lane covers pos lane*4..lane*4+3

    float4 av0 = {0,0,0,0}, av1 = {0,0,0,0}, av2 = {0,0,0,0}, av3 = {0,0,0,0};
    const float NI = -3.402823466e38f;
    float4 mx0 = {NI,NI,NI,NI}, mx1 = mx0, mx2 = mx0, mx3 = mx0;

    const int cbase = warp * 32;
    #pragma unroll 2
    for (int cc = 0; cc < 32; cc++) {
        const int c = cbase + cc;
        const size_t row = (size_t)c * (HWn / 4) + p4base;
        float4 v0 = __ldg(&xb[row]);
        float4 v1 = __ldg(&xb[row + 32]);
        float4 v2 = __ldg(&xb[row + 64]);
        float4 v3 = __ldg(&xb[row + 96]);

        av0.x += v0.x; av0.y += v0.y; av0.z += v0.z; av0.w += v0.w;
        av1.x += v1.x; av1.y += v1.y; av1.z += v1.z; av1.w += v1.w;
        av2.x += v2.x; av2.y += v2.y; av2.z += v2.z; av2.w += v2.w;
        av3.x += v3.x; av3.y += v3.y; av3.z += v3.z; av3.w += v3.w;
        mx0.x = fmaxf(mx0.x, v0.x); mx0.y = fmaxf(mx0.y, v0.y); mx0.z = fmaxf(mx0.z, v0.z); mx0.w = fmaxf(mx0.w, v0.w);
        mx1.x = fmaxf(mx1.x, v1.x); mx1.y = fmaxf(mx1.y, v1.y); mx1.z = fmaxf(mx1.z, v1.z); mx1.w = fmaxf(mx1.w, v1.w);
        mx2.x = fmaxf(mx2.x, v2.x); mx2.y = fmaxf(mx2.y, v2.y); mx2.z = fmaxf(mx2.z, v2.z); mx2.w = fmaxf(mx2.w, v2.w);
        mx3.x = fmaxf(mx3.x, v3.x); mx3.y = fmaxf(mx3.y, v3.y); mx3.z = fmaxf(mx3.z, v3.z); mx3.w = fmaxf(mx3.w, v3.w);

        float r = ((v0.x + v0.y) + (v0.z + v0.w)) + ((v1.x + v1.y) + (v1.z + v1.w))
                + ((v2.x + v2.y) + (v2.z + v2.w)) + ((v3.x + v3.y) + (v3.z + v3.w));
        #pragma unroll
        for (int o = 16; o; o >>= 1) r += __shfl_xor_sync(0xffffffffu, r, o);
        if (lane == 0) d_gpart[(b * 8 + tile) * Cn + c] = r;
    }

    // publish per-warp av/mx partials (warp covered only its 32 channels)
    *(float4*)&avp[warp][lane * 4]       = av0;
    *(float4*)&avp[warp][128 + lane * 4] = av1;
    *(float4*)&avp[warp][256 + lane * 4] = av2;
    *(float4*)&avp[warp][384 + lane * 4] = av3;
    *(float4*)&mxp[warp][lane * 4]       = mx0;
    *(float4*)&mxp[warp][128 + lane * 4] = mx1;
    *(float4*)&mxp[warp][256 + lane * 4] = mx2;
    *(float4*)&mxp[warp][384 + lane * 4] = mx3;
    __syncthreads();

    #pragma unroll
    for (int p = t; p < 512; p += 256) {
        float s = 0.f, m = NI;
        #pragma unroll
        for (int w = 0; w < 8; w++) { s += avp[w][p]; m = fmaxf(m, mxp[w][p]); }
        d_av[b * HWn + pos0 + p] = s * (1.f / (float)Cn);
        d_mx[b * HWn + pos0 + p] = m;
    }
}

// ---------------- K2: per-batch MLP head ----------------
__global__ void k2_mlp(const float* __restrict__ a,
                       const float* __restrict__ W_pre, const float* __restrict__ b_pre,
                       const float* __restrict__ W_bc,  const float* __restrict__ b_bc,
                       const float* __restrict__ W_bs,  const float* __restrict__ b_bs,
                       const float* __restrict__ W_pc,  const float* __restrict__ b_pc,
                       const float* __restrict__ W_ps,  const float* __restrict__ b_ps,
                       const float* __restrict__ W_Ws,  const float* __restrict__ b_Ws) {
    const int b = blockIdx.x;
    const int t = threadIdx.x;

    __shared__ float in_s[Cn + AUXn];
    __shared__ float h_s[HIDn];
    __shared__ float phic_s[RANKn], phis_s[RANKn];
    __shared__ float mbs_s[OSn], sm_s[OSn];
    __shared__ float sred[OSn * RANKn];

    {
        float g = 0.f;
        #pragma unroll
        for (int tl = 0; tl < 8; tl++) g += d_gpart[(b * 8 + tl) * Cn + t];
        in_s[t] = g * (1.f / (float)HWn);
        if (t < AUXn) in_s[Cn + t] = __ldg(a + b * AUXn + t);
    }
    __syncthreads();

    // h = relu(in @ W_pre + b_pre), dual accumulators for ILP
    {
        float a0 = __ldg(b_pre + t), a1 = 0.f;
        #pragma unroll 4
        for (int i = 0; i < Cn + AUXn; i += 2) {
            a0 = fmaf(in_s[i],     __ldg(W_pre + i * HIDn + t), a0);
            a1 = fmaf(in_s[i + 1], __ldg(W_pre + (i + 1) * HIDn + t), a1);
        }
        float h = fmaxf(a0 + a1, 0.f);
        h_s[t] = h;
        d_h[b * HIDn + t] = h;
    }
    __syncthreads();

    // m_base_c
    {
        float a0 = __ldg(b_bc + t), a1 = 0.f;
        #pragma unroll 4
        for (int k = 0; k < HIDn; k += 2) {
            a0 = fmaf(h_s[k],     __ldg(W_bc + k * Cn + t), a0);
            a1 = fmaf(h_s[k + 1], __ldg(W_bc + (k + 1) * Cn + t), a1);
        }
        d_mbc[b * Cn + t] = a0 + a1;
    }
    if (t < 32) {
        float p = __ldg(b_pc + t);
        #pragma unroll 4
        for (int k = 0; k < HIDn; k++)
            p = fmaf(h_s[k], __ldg(W_pc + k * RANKn + t), p);
        float w = 1.f + (PI_F - 1.f) * (float)t / 31.f;
        float u = p * w;
        phic_s[t]      = sinf(u);
        phic_s[t + 32] = cosf(u);
    } else if (t < 64) {
        int r = t - 32;
        float p = __ldg(b_ps + r);
        #pragma unroll 4
        for (int k = 0; k < HIDn; k++)
            p = fmaf(h_s[k], __ldg(W_ps + k * RANKn + r), p);
        float w = 1.f + (PI_F - 1.f) * (float)r / 31.f;
        float u = p * w;
        phis_s[r]      = sinf(u);
        phis_s[r + 32] = cosf(u);
    } else if (t < 64 + OSn) {
        int s = t - 64;
        float mbs = __ldg(b_bs + s);
        for (int k = 0; k < HIDn; k++)
            mbs = fmaf(h_s[k], __ldg(W_bs + k * OSn + s), mbs);
        mbs_s[s] = mbs;
    }
    __syncthreads();

    if (t < RANKn) d_phic[b * RANKn + t] = phic_s[t];
    #pragma unroll
    for (int o = t; o < OSn * RANKn; o += 256) {
        int r = o & 63;
        float ws = __ldg(b_Ws + o);
        #pragma unroll 4
        for (int k = 0; k < HIDn; k++)
            ws = fmaf(h_s[k], __ldg(W_Ws + k * (OSn * RANKn) + o), ws);
        sred[o] = ws * phis_s[r];
    }
    __syncthreads();

    if (t < OSn) {
        float sm = 0.f;
        #pragma unroll
        for (int r = 0; r < RANKn; r++) sm += sred[t * RANKn + r];
        sm_s[t] = mbs_s[t] * sm;
    }
    __syncthreads();

    if (t < OSn) {
        d_pco[b * 10 + (t >> 2) * 5 + (t & 3)] = sm_s[t];
    } else if (t < OSn + 2) {
        int j = t - OSn;
        float cc = -(sm_s[j * 4] + sm_s[j * 4 + 1] + sm_s[j * 4 + 2] + sm_s[j * 4 + 3]);
        d_pco[b * 10 + j * 5 + 4] = cc;
    }
}

// ---------------- K3: E[b,c] = sum_{k,r} h[b,k] phi[b,r] W_Wc[k, c*64+r]  (+ bias split) ----------------
// grid (32 c-tiles, 9 splits): ks<8 are 32-wide k-splits of W_Wc; ks==8 is the b_Wc bias dot.
// lane = b, warp = c within tile. W read exactly once chip-wide (broadcast across b-lanes).
__global__ void k3_einsum(const float* __restrict__ W_Wc, const float* __restrict__ b_Wc) {
    const int ct = blockIdx.x;
    const int ks = blockIdx.y;
    const int t  = threadIdx.x;
    const int lane = t & 31;     // = b
    const int warp = t >> 5;
    const int c = ct * 8 + warp;

    __shared__ float h_s[32 * 33];
    __shared__ float phi_s[32 * 68];

    if (ks < 8) {
        for (int i = t; i < 32 * 32; i += 256) {
            int bb = i >> 5, kk = i & 31;
            h_s[bb * 33 + kk] = d_h[bb * HIDn + ks * 32 + kk];
        }
    }
    for (int i = t; i < 32 * 64; i += 256) {
        int bb = i >> 6, r = i & 63;
        phi_s[bb * 68 + r] = d_phic[bb * RANKn + r];
    }
    __syncthreads();

    float acc = 0.f;
    if (ks < 8) {
        const float* Wbase = W_Wc + (size_t)(ks * 32) * (Cn * RANKn) + c * RANKn;
        #pragma unroll 2
        for (int kk = 0; kk < 32; kk++) {
            float hk = h_s[lane * 33 + kk];
            const float4* w4 = (const float4*)(Wbase + (size_t)kk * (Cn * RANKn));
            float dot = 0.f;
            #pragma unroll
            for (int r4 = 0; r4 < 16; r4++) {
                float4 w = __ldg(&w4[r4]);   // broadcast across lanes
                float4 p = *(const float4*)(phi_s + lane * 68 + r4 * 4);
                dot = fmaf(w.x, p.x, dot);
                dot = fmaf(w.y, p.y, dot);
                dot = fmaf(w.z, p.z, dot);
                dot = fmaf(w.w, p.w, dot);
            }
            acc = fmaf(hk, dot, acc);
        }
    } else {
        const float4* bw4 = (const float4*)(b_Wc + c * RANKn);
        #pragma unroll
        for (int r4 = 0; r4 < 16; r4++) {
            float4 w = __ldg(&bw4[r4]);      // broadcast across lanes
            float4 p = *(const float4*)(phi_s + lane * 68 + r4 * 4);
            acc = fmaf(w.x, p.x, acc);
            acc = fmaf(w.y, p.y, acc);
            acc = fmaf(w.z, p.z, acc);
            acc = fmaf(w.w, p.w, acc);
        }
    }
    d_Ep[(lane * 9 + ks) * Cn + c] = acc;
}

// ---------------- K4: reduce 9 partials -> sigmoid(c_m); fully coalesced ----------------
__global__ void k4_sigc() {
    const int b = blockIdx.x;
    const int c = threadIdx.x;
    float e = 0.f;
    #pragma unroll
    for (int ks = 0; ks < 9; ks++) e += d_Ep[(b * 9 + ks) * Cn + c];
    float cm = d_mbc[b * Cn + c] * e;
    d_sigc[b * Cn + c] = 1.f / (1.f + expf(-cm));
}

// ---------------- K4b: stencil on (av, mx) -> sigmoid(conv) ----------------
__global__ void k4b_conv() {
    const int b  = blockIdx.y;
    const int hw = blockIdx.x * 256 + threadIdx.x;
    const int hh = hw >> 6, ww = hw & 63;
    __shared__ float pc[10];
    if (threadIdx.x < 10) pc[threadIdx.x] = d_pco[b * 10 + threadIdx.x];
    __syncthreads();

    const float* av = d_av + b * HWn;
    const float* mx = d_mx + b * HWn;

    float up_a = (hh > 0)      ? av[hw - Wn] : 0.f;
    float dn_a = (hh < Hn - 1) ? av[hw + Wn] : 0.f;
    float lf_a = (ww > 0)      ? av[hw - 1]  : 0.f;
    float rt_a = (ww < Wn - 1) ? av[hw + 1]  : 0.f;
    float ce_a = av[hw];
    float up_m = (hh > 0)      ? mx[hw - Wn] : 0.f;
    float dn_m = (hh < Hn - 1) ? mx[hw + Wn] : 0.f;
    float lf_m = (ww > 0)      ? mx[hw - 1]  : 0.f;
    float rt_m = (ww < Wn - 1) ? mx[hw + 1]  : 0.f;
    float ce_m = mx[hw];

    float conv = pc[0] * up_a + pc[1] * dn_a + pc[2] * lf_a + pc[3] * rt_a + pc[4] * ce_a
               + pc[5] * up_m + pc[6] * dn_m + pc[7] * lf_m + pc[8] * rt_m + pc[9] * ce_m;
    d_convsig[b * HWn + hw] = 1.f / (1.f + expf(-conv));
}

// ---------------- K5: output pass ----------------
__global__ void k5_out(const float* __restrict__ x, float* __restrict__ out) {
    const int t   = threadIdx.x;
    const int hw4 = blockIdx.x * 256 + t;
    const int bcg = blockIdx.y;
    const int b   = bcg >> 3;
    const int cg  = bcg & 7;

    const float4 cv = ((const float4*)d_convsig)[b * (HWn / 4) + hw4];
    const float* sc = d_sigc + b * Cn + cg * 32;

    const size_t base = ((size_t)(b * Cn + cg * 32)) * (HWn / 4) + hw4;
    const float4* x4 = (const float4*)x;
    float4* o4 = (float4*)out;

    #pragma unroll 8
    for (int ci = 0; ci < 32; ci++) {
        float s = __ldg(sc + ci) + 1.f;
        float4 v = __ldg(&x4[base + (size_t)ci * (HWn / 4)]);
        float4 o;
        o.x = v.x * (s + cv.x);
        o.y = v.y * (s + cv.y);
        o.z = v.z * (s + cv.z);
        o.w = v.w * (s + cv.w);
        o4[base + (size_t)ci * (HWn / 4)] = o;
    }
}

// ---------------- launch ----------------
extern "C" void kernel_launch(void* const* d_in, const int* in_sizes, int n_in,
                              void* d_out, int out_size) {
    (void)in_sizes; (void)n_in; (void)out_size;
    const float* x     = (const float*)d_in[0];
    const float* a     = (const float*)d_in[1];
    const float* W_pre = (const float*)d_in[2];
    const float* b_pre = (const float*)d_in[3];
    const float* W_bc  = (const float*)d_in[4];
    const float* b_bc  = (const float*)d_in[5];
    const float* W_bs  = (const float*)d_in[6];
    const float* b_bs  = (const float*)d_in[7];
    const float* W_pc  = (const float*)d_in[8];
    const float* b_pc  = (const float*)d_in[9];
    const float* W_ps  = (const float*)d_in[10];
    const float* b_ps  = (const float*)d_in[11];
    const float* W_Wc  = (const float*)d_in[12];
    const float* b_Wc  = (const float*)d_in[13];
    const float* W_Ws  = (const float*)d_in[14];
    const float* b_Ws  = (const float*)d_in[15];
    float* out = (float*)d_out;

    k1_stats <<<dim3(8, Bn), 256>>>(x);
    k2_mlp   <<<Bn, 256>>>(a, W_pre, b_pre, W_bc, b_bc, W_bs, b_bs,
                           W_pc, b_pc, W_ps, b_ps, W_Ws, b_Ws);
    k3_einsum<<<dim3(32, 9), 256>>>(W_Wc, b_Wc);
    k4_sigc  <<<Bn, 256>>>();
    k4b_conv <<<dim3(16, Bn), 256>>>();
    k5_out   <<<dim3(4, Bn * 8), 256>>>(x, out);
}